// round 15
// baseline (speedup 1.0000x reference)
#include <cuda_runtime.h>

// InverseHaar: input (B=16, C=256, H=128, W=128) fp32, C = 4 bands x G=64 groups.
// Output (B=16, G=64, 2H=256, 2W=256) fp32.
//
// FINAL (converged; measured 80.35/80.38/81.02/81.34/81.38 us over five
// independent runs of this exact binary). One thread per (b, g, h, half, l).
// Lane l handles input w in {2l, 2l+1} of the `half`-th half-row:
//   - 4 front-batched LDG.64 streaming loads (256B/warp/band, 4 streams)
//   - 2 STG.128 streaming stores, each warp-contiguous 512B (full-line
//     coverage -> zero RFO traffic)
// Moves the irreducible 537MB; pinned at the HBM3e mixed 1:1 read/write
// streaming wall (~6.45-6.53 TB/s, ~81.5% DRAM-active). Ceiling proven
// invariant to: access pattern (direct 4-stream vs SMEM-staged 1-stream),
// MLP (4/8/16), occupancy (51-92%), block size (256/512), persistent vs
// classic scheduling, L1/L2 cache policies, and addressing width.
// 32-bit addressing (max offset 2^27 elements < 2^31).

#define B_  16
#define G_  64
#define H_  128
#define W_  128
#define HW_ (H_ * W_)              // 16384
#define BAND_STRIDE_ (G_ * HW_)    // 1048576 floats between bands (same b)
#define OW_ (2 * W_)               // 256 output width
#define OH_ (2 * H_)               // 256 output height

__global__ void __launch_bounds__(256) inverse_haar_kernel(
    const float2* __restrict__ in,   // viewed as float2
    float4* __restrict__ out)        // viewed as float4
{
    unsigned idx = blockIdx.x * blockDim.x + threadIdx.x;
    // total threads = B*G*H*2*32 = 8,388,608

    unsigned l    = idx & 31;       // lane: w pair within half-row
    unsigned t    = idx >> 5;
    unsigned half = t & 1;          // which half of the input row (w<64 or w>=64)
    t >>= 1;
    unsigned h    = t & (H_ - 1);
    t >>= 7;
    unsigned g    = t & (G_ - 1);
    unsigned b    = t >> 6;

    // Input base in float2 units: band a, (b,g,h) row, pair index half*32 + l.
    unsigned base = (b * 4 * G_ + g) * (HW_ / 2) + h * (W_ / 2) + half * 32 + l;
    const unsigned S = BAND_STRIDE_ / 2;   // band stride in float2 units

    // 4 independent streaming loads (MLP_p1 = 4)
    float2 va = __ldcs(&in[base]);
    float2 vh = __ldcs(&in[base + S]);
    float2 vv = __ldcs(&in[base + 2 * S]);
    float2 vd = __ldcs(&in[base + 3 * S]);

    const float Q = 0.25f;

    float tlx = (va.x + vh.x + vv.x + vd.x) * Q;
    float trx = (va.x - vh.x + vv.x - vd.x) * Q;
    float blx = (va.x + vh.x - vv.x - vd.x) * Q;
    float brx = (va.x - vh.x - vv.x + vd.x) * Q;

    float tly = (va.y + vh.y + vv.y + vd.y) * Q;
    float try_ = (va.y - vh.y + vv.y - vd.y) * Q;
    float bly = (va.y + vh.y - vv.y - vd.y) * Q;
    float bry = (va.y - vh.y - vv.y + vd.y) * Q;

    // Output row bases (float4 units). Row has OW_/4 = 64 float4.
    // This thread's float4 slot within the row: half*32 + l.
    unsigned orow0 = ((b * G_ + g) * OH_ + 2 * h) * (OW_ / 4) + half * 32 + l;
    unsigned orow1 = orow0 + (OW_ / 4);

    // Each store: lanes 0..31 hit consecutive 16B slots -> contiguous 512B.
    __stcs(&out[orow0], make_float4(tlx, trx, tly, try_));
    __stcs(&out[orow1], make_float4(blx, brx, bly, bry));
}

extern "C" void kernel_launch(void* const* d_in, const int* in_sizes, int n_in,
                              void* d_out, int out_size)
{
    const float2* in = (const float2*)d_in[0];
    float4* out = (float4*)d_out;

    int total_threads = B_ * G_ * H_ * 2 * 32;   // 8,388,608
    int block = 256;
    int grid = total_threads / block;            // 32768
    inverse_haar_kernel<<<grid, block>>>(in, out);
}

// round 16
// speedup vs baseline: 1.0139x; 1.0139x over previous
#include <cuda_runtime.h>

// InverseHaar: input (B=16, C=256, H=128, W=128) fp32, C = 4 bands x G=64 groups.
// Output (B=16, G=64, 2H=256, 2W=256) fp32.
//
// FINAL (converged; measured 80.35/80.38/81.02/81.34/81.38/81.47 us over six
// independent runs of this exact binary). One thread per (b, g, h, half, l).
// Lane l handles input w in {2l, 2l+1} of the `half`-th half-row:
//   - 4 front-batched LDG.64 streaming loads (256B/warp/band, 4 streams)
//   - 2 STG.128 streaming stores, each warp-contiguous 512B (full-line
//     coverage -> zero RFO traffic)
// Moves the irreducible 537MB; pinned at the HBM3e mixed 1:1 read/write
// streaming wall (~6.45-6.53 TB/s, ~81.5% DRAM-active). Ceiling proven
// invariant to: access pattern (direct 4-stream vs SMEM-staged 1-stream),
// MLP (4/8/16), occupancy (51-92%), block size (256/512), persistent vs
// classic scheduling, L1/L2 cache policies, and addressing width.
// 32-bit addressing (max offset 2^27 elements < 2^31).

#define B_  16
#define G_  64
#define H_  128
#define W_  128
#define HW_ (H_ * W_)              // 16384
#define BAND_STRIDE_ (G_ * HW_)    // 1048576 floats between bands (same b)
#define OW_ (2 * W_)               // 256 output width
#define OH_ (2 * H_)               // 256 output height

__global__ void __launch_bounds__(256) inverse_haar_kernel(
    const float2* __restrict__ in,   // viewed as float2
    float4* __restrict__ out)        // viewed as float4
{
    unsigned idx = blockIdx.x * blockDim.x + threadIdx.x;
    // total threads = B*G*H*2*32 = 8,388,608

    unsigned l    = idx & 31;       // lane: w pair within half-row
    unsigned t    = idx >> 5;
    unsigned half = t & 1;          // which half of the input row (w<64 or w>=64)
    t >>= 1;
    unsigned h    = t & (H_ - 1);
    t >>= 7;
    unsigned g    = t & (G_ - 1);
    unsigned b    = t >> 6;

    // Input base in float2 units: band a, (b,g,h) row, pair index half*32 + l.
    unsigned base = (b * 4 * G_ + g) * (HW_ / 2) + h * (W_ / 2) + half * 32 + l;
    const unsigned S = BAND_STRIDE_ / 2;   // band stride in float2 units

    // 4 independent streaming loads (MLP_p1 = 4)
    float2 va = __ldcs(&in[base]);
    float2 vh = __ldcs(&in[base + S]);
    float2 vv = __ldcs(&in[base + 2 * S]);
    float2 vd = __ldcs(&in[base + 3 * S]);

    const float Q = 0.25f;

    float tlx = (va.x + vh.x + vv.x + vd.x) * Q;
    float trx = (va.x - vh.x + vv.x - vd.x) * Q;
    float blx = (va.x + vh.x - vv.x - vd.x) * Q;
    float brx = (va.x - vh.x - vv.x + vd.x) * Q;

    float tly = (va.y + vh.y + vv.y + vd.y) * Q;
    float try_ = (va.y - vh.y + vv.y - vd.y) * Q;
    float bly = (va.y + vh.y - vv.y - vd.y) * Q;
    float bry = (va.y - vh.y - vv.y + vd.y) * Q;

    // Output row bases (float4 units). Row has OW_/4 = 64 float4.
    // This thread's float4 slot within the row: half*32 + l.
    unsigned orow0 = ((b * G_ + g) * OH_ + 2 * h) * (OW_ / 4) + half * 32 + l;
    unsigned orow1 = orow0 + (OW_ / 4);

    // Each store: lanes 0..31 hit consecutive 16B slots -> contiguous 512B.
    __stcs(&out[orow0], make_float4(tlx, trx, tly, try_));
    __stcs(&out[orow1], make_float4(blx, brx, bly, bry));
}

extern "C" void kernel_launch(void* const* d_in, const int* in_sizes, int n_in,
                              void* d_out, int out_size)
{
    const float2* in = (const float2*)d_in[0];
    float4* out = (float4*)d_out;

    int total_threads = B_ * G_ * H_ * 2 * 32;   // 8,388,608
    int block = 256;
    int grid = total_threads / block;            // 32768
    inverse_haar_kernel<<<grid, block>>>(in, out);
}